// round 3
// baseline (speedup 1.0000x reference)
#include <cuda_runtime.h>

#define NROWS   341
#define CSTRIDE 16
#define TPB     128
#define SPT     4          // samples per thread = 2 packed pairs
#define NSAMP   262144

typedef unsigned long long u64;

// Duplicated-pair coefficient table: element m of row r stored as (c,c).
__device__ float2 gC2[NROWS * CSTRIDE];

// ---------------- packed f32x2 helpers ----------------
__device__ __forceinline__ u64 pk2(float a, float b) {
    u64 r; asm("mov.b64 %0,{%1,%2};" : "=l"(r) : "f"(a), "f"(b)); return r;
}
__device__ __forceinline__ void upk2(u64 d, float& a, float& b) {
    asm("mov.b64 {%0,%1},%2;" : "=f"(a), "=f"(b) : "l"(d));
}
__device__ __forceinline__ u64 fma2_(u64 a, u64 b, u64 c) {
    u64 d; asm("fma.rn.f32x2 %0,%1,%2,%3;" : "=l"(d) : "l"(a), "l"(b), "l"(c)); return d;
}
__device__ __forceinline__ u64 mul2_(u64 a, u64 b) {
    u64 d; asm("mul.rn.f32x2 %0,%1,%2;" : "=l"(d) : "l"(a), "l"(b)); return d;
}

// ---------------------------------------------------------------------------
// Prep: constrained(A) = 2*(sigmoid(cumsum(softplus(A), axis=1)) - 0.5)
// ---------------------------------------------------------------------------
__global__ void bf_prep(const float* __restrict__ A0, const float* __restrict__ A1,
                        const float* __restrict__ A2, const float* __restrict__ A3,
                        const float* __restrict__ A4) {
    int r = threadIdx.x;
    if (r >= NROWS) return;
    const float* A; int lr;
    if (r == 0)      { A = A0; lr = 0;      }
    else if (r < 5)  { A = A1; lr = r - 1;  }
    else if (r < 21) { A = A2; lr = r - 5;  }
    else if (r < 85) { A = A3; lr = r - 21; }
    else             { A = A4; lr = r - 85; }
    float s = 0.f;
    for (int m = 0; m < 15; m++) {
        float a  = A[lr * 15 + m];
        float sp = (a > 20.f) ? a : log1pf(expf(a));
        s += sp;
        float sig = 1.f / (1.f + expf(-s));
        float v = 2.f * (sig - 0.5f);
        gC2[r * CSTRIDE + m] = make_float2(v, v);
    }
    gC2[r * CSTRIDE + 15] = make_float2(0.f, 0.f);
}

// ---------------------------------------------------------------------------
// One coefficient row, both packed pairs: acc += w * C[row]
// 7x LDS.128 (pairs 0..13) + 1x LDS.64 (pair 14); element 15 untouched.
// ---------------------------------------------------------------------------
__device__ __forceinline__ void row2(const u64* __restrict__ sC2, int row,
                                     u64 wA, u64 wB, u64 aA[16], u64 aB[16]) {
    const ulonglong2* p = reinterpret_cast<const ulonglong2*>(sC2 + row * CSTRIDE);
#pragma unroll
    for (int q = 0; q < 7; q++) {
        ulonglong2 c = p[q];
        aA[2*q]     = fma2_(wA, c.x, aA[2*q]);
        aA[2*q + 1] = fma2_(wA, c.y, aA[2*q + 1]);
        aB[2*q]     = fma2_(wB, c.x, aB[2*q]);
        aB[2*q + 1] = fma2_(wB, c.y, aB[2*q + 1]);
    }
    u64 c14 = sC2[row * CSTRIDE + 14];
    aA[14] = fma2_(wA, c14, aA[14]);
    aB[14] = fma2_(wB, c14, aB[14]);
}

// ---------------------------------------------------------------------------
// Packed derivative eval for both pairs.
// f = sum_m (acc[m]-acc[m-1]) * comb16[m] * u^m v^(15-m), acc[15]==1.
// ---------------------------------------------------------------------------
__device__ __forceinline__ void deriv2x2(const u64 aA[16], const u64 aB[16],
                                         u64 uA, u64 uB, u64& fA, u64& fB) {
    const float comb[15] = {16.f, 240.f, 1680.f, 7280.f, 21840.f, 48048.f,
                            80080.f, 102960.f, 102960.f, 80080.f, 48048.f,
                            21840.f, 7280.f, 1680.f, 240.f};
    u64 one2 = pk2(1.f, 1.f);
    u64 neg1 = pk2(-1.f, -1.f);
    u64 c16  = pk2(16.f, 16.f);
    u64 vA = fma2_(uA, neg1, one2);
    u64 vB = fma2_(uB, neg1, one2);
    u64 FA = mul2_(fma2_(aA[14], neg1, aA[15]), c16);
    u64 FB = mul2_(fma2_(aB[14], neg1, aB[15]), c16);
    u64 vpA = one2, vpB = one2;
#pragma unroll
    for (int m = 14; m >= 0; m--) {
        u64 c2 = pk2(comb[m], comb[m]);
        u64 pA = (m > 0) ? aA[m - 1] : 0ULL;
        u64 pB = (m > 0) ? aB[m - 1] : 0ULL;
        u64 sA = mul2_(fma2_(pA, neg1, aA[m]), c2);
        u64 sB = mul2_(fma2_(pB, neg1, aB[m]), c2);
        vpA = mul2_(vpA, vA);
        vpB = mul2_(vpB, vB);
        FA = fma2_(uA, FA, mul2_(sA, vpA));
        FB = fma2_(uB, FB, mul2_(sB, vpB));
    }
    fA = FA; fB = FB;
}

// ---------------------------------------------------------------------------
// Main kernel: 4 samples per thread as 2 f32x2 pairs.
// ---------------------------------------------------------------------------
__global__ void __launch_bounds__(TPB)
bf_main(const float* __restrict__ x, float* __restrict__ out) {
    __shared__ __align__(16) u64 sC2[NROWS * CSTRIDE];

    const int tid  = threadIdx.x;
    const int base = blockIdx.x * (TPB * SPT);

    // stage duplicated coefficient table (43.6 KB) via 16B copies
    {
        const uint4* src = reinterpret_cast<const uint4*>(gC2);
        uint4*       dst = reinterpret_cast<uint4*>(sC2);
        const int n16 = NROWS * CSTRIDE * 8 / 16;   // 2728
        for (int i = tid; i < n16; i += TPB) dst[i] = src[i];
    }
    __syncthreads();

    const int s0 = base + tid;          // pair A = (s0, s1), pair B = (s2, s3)
    const int s1 = s0 + TPB;
    const int s2 = s0 + 2 * TPB;
    const int s3 = s0 + 3 * TPB;

    u64 xA[5], xB[5];
#pragma unroll
    for (int j = 0; j < 5; j++) {
        xA[j] = pk2(x[s0 * 5 + j], x[s1 * 5 + j]);
        xB[j] = pk2(x[s2 * 5 + j], x[s3 * 5 + j]);
    }

    const u64 one2 = pk2(1.f, 1.f);
    const u64 neg1 = pk2(-1.f, -1.f);
    const u64 thr2 = pk2(3.f, 3.f);

    // degree-3 Bernstein bases for conditioner coords 0..3, both pairs
    u64 bA[4][4], bB[4][4];
#pragma unroll
    for (int j = 0; j < 4; j++) {
        u64 u = xA[j], v = fma2_(u, neg1, one2);
        u64 uu = mul2_(u, u), vv = mul2_(v, v);
        bA[j][0] = mul2_(vv, v);
        bA[j][1] = mul2_(mul2_(u, vv), thr2);
        bA[j][2] = mul2_(mul2_(uu, v), thr2);
        bA[j][3] = mul2_(uu, u);
        u  = xB[j]; v = fma2_(u, neg1, one2);
        uu = mul2_(u, u); vv = mul2_(v, v);
        bB[j][0] = mul2_(vv, v);
        bB[j][1] = mul2_(mul2_(u, vv), thr2);
        bB[j][2] = mul2_(mul2_(uu, v), thr2);
        bB[j][3] = mul2_(uu, u);
    }

    u64 dA, dB, fA, fB;

    // ---- dim 0: single row, weight 1 (coeffs already duplicated pairs)
    {
        u64 acc[16];
#pragma unroll
        for (int m = 0; m < 15; m++) acc[m] = sC2[m];
        acc[15] = one2;
        deriv2x2(acc, acc, xA[0], xB[0], dA, dB);
    }

    // ---- dim 1 (rowbase 1)
    {
        u64 aA[16], aB[16];
#pragma unroll
        for (int m = 0; m < 15; m++) { aA[m] = 0ULL; aB[m] = 0ULL; }
        aA[15] = one2; aB[15] = one2;
#pragma unroll
        for (int k0 = 0; k0 < 4; k0++)
            row2(sC2, 1 + k0, bA[0][k0], bB[0][k0], aA, aB);
        deriv2x2(aA, aB, xA[1], xB[1], fA, fB);
        dA = mul2_(dA, fA); dB = mul2_(dB, fB);
    }

    // ---- dim 2 (rowbase 5)
    {
        u64 aA[16], aB[16];
#pragma unroll
        for (int m = 0; m < 15; m++) { aA[m] = 0ULL; aB[m] = 0ULL; }
        aA[15] = one2; aB[15] = one2;
#pragma unroll
        for (int k0 = 0; k0 < 4; k0++) {
            u64 wA0 = bA[0][k0], wB0 = bB[0][k0];
#pragma unroll
            for (int k1 = 0; k1 < 4; k1++) {
                row2(sC2, 5 + k0 * 4 + k1,
                     mul2_(wA0, bA[1][k1]), mul2_(wB0, bB[1][k1]), aA, aB);
            }
        }
        deriv2x2(aA, aB, xA[2], xB[2], fA, fB);
        dA = mul2_(dA, fA); dB = mul2_(dB, fB);
    }

    // ---- dim 3 (rowbase 21)
    {
        u64 aA[16], aB[16];
#pragma unroll
        for (int m = 0; m < 15; m++) { aA[m] = 0ULL; aB[m] = 0ULL; }
        aA[15] = one2; aB[15] = one2;
#pragma unroll
        for (int k0 = 0; k0 < 4; k0++) {
            u64 wA0 = bA[0][k0], wB0 = bB[0][k0];
#pragma unroll
            for (int k1 = 0; k1 < 4; k1++) {
                u64 wA1 = mul2_(wA0, bA[1][k1]), wB1 = mul2_(wB0, bB[1][k1]);
#pragma unroll
                for (int k2 = 0; k2 < 4; k2++) {
                    row2(sC2, 21 + (k0 * 4 + k1) * 4 + k2,
                         mul2_(wA1, bA[2][k2]), mul2_(wB1, bB[2][k2]), aA, aB);
                }
            }
        }
        deriv2x2(aA, aB, xA[3], xB[3], fA, fB);
        dA = mul2_(dA, fA); dB = mul2_(dB, fB);
    }

    // ---- dim 4 (rowbase 85)
    {
        u64 aA[16], aB[16];
#pragma unroll
        for (int m = 0; m < 15; m++) { aA[m] = 0ULL; aB[m] = 0ULL; }
        aA[15] = one2; aB[15] = one2;
#pragma unroll
        for (int k0 = 0; k0 < 4; k0++) {
            u64 wA0 = bA[0][k0], wB0 = bB[0][k0];
#pragma unroll
            for (int k1 = 0; k1 < 4; k1++) {
                u64 wA1 = mul2_(wA0, bA[1][k1]), wB1 = mul2_(wB0, bB[1][k1]);
#pragma unroll
                for (int k2 = 0; k2 < 4; k2++) {
                    u64 wA2 = mul2_(wA1, bA[2][k2]), wB2 = mul2_(wB1, bB[2][k2]);
#pragma unroll
                    for (int k3 = 0; k3 < 4; k3++) {
                        row2(sC2, 85 + ((k0 * 4 + k1) * 4 + k2) * 4 + k3,
                             mul2_(wA2, bA[3][k3]), mul2_(wB2, bB[3][k3]), aA, aB);
                    }
                }
            }
        }
        deriv2x2(aA, aB, xA[4], xB[4], fA, fB);
        dA = mul2_(dA, fA); dB = mul2_(dB, fB);
    }

    float r0, r1, r2, r3;
    upk2(dA, r0, r1);
    upk2(dB, r2, r3);
    out[s0] = r0; out[s1] = r1; out[s2] = r2; out[s3] = r3;
}

// ---------------------------------------------------------------------------
extern "C" void kernel_launch(void* const* d_in, const int* in_sizes, int n_in,
                              void* d_out, int out_size) {
    const float* x  = (const float*)d_in[0];
    const float* A0 = (const float*)d_in[1];
    const float* A1 = (const float*)d_in[2];
    const float* A2 = (const float*)d_in[3];
    const float* A3 = (const float*)d_in[4];
    const float* A4 = (const float*)d_in[5];
    float* out = (float*)d_out;

    bf_prep<<<1, 352>>>(A0, A1, A2, A3, A4);
    bf_main<<<NSAMP / (TPB * SPT), TPB>>>(x, out);
}